// round 10
// baseline (speedup 1.0000x reference)
#include <cuda_runtime.h>
#include <cuda_bf16.h>

// TopKPool_16372415332892
// out[b] = (1/K) * sum_{topK rows} x[row] * tanh((x[row].w)/||w||)
// B=256, N=512, D=256, K=256. edge_index/batch dead inputs.

#define BB 256
#define NN 512
#define DD 256
#define KK 256

__device__ float g_score[BB * NN];   // raw dot products (selection monotone in this)
__device__ int2  g_sel[BB * KK];     // {node idx, gate bits}, compacted by rank

// ---------------- Kernel 1: scores (4 rows per warp -> 8 indep LDG.128/thread) ----------------
// grid = B*N/32 = 4096 blocks, 256 threads (8 warps x 4 rows = 32 rows/block).
__global__ __launch_bounds__(256)
void score_kernel(const float* __restrict__ x, const float* __restrict__ w)
{
    const int lane = threadIdx.x & 31;
    const int warp = threadIdx.x >> 5;
    const int row0 = blockIdx.x * 32 + warp * 4;

    const float4 wa = *reinterpret_cast<const float4*>(w + lane * 4);
    const float4 wb = *reinterpret_cast<const float4*>(w + 128 + lane * 4);

    const float* r0 = x + (size_t)row0 * DD;
    const float4 a0 = *reinterpret_cast<const float4*>(r0 + lane * 4);
    const float4 c0 = *reinterpret_cast<const float4*>(r0 + 128 + lane * 4);
    const float4 a1 = *reinterpret_cast<const float4*>(r0 + DD + lane * 4);
    const float4 c1 = *reinterpret_cast<const float4*>(r0 + DD + 128 + lane * 4);
    const float4 a2 = *reinterpret_cast<const float4*>(r0 + 2 * DD + lane * 4);
    const float4 c2 = *reinterpret_cast<const float4*>(r0 + 2 * DD + 128 + lane * 4);
    const float4 a3 = *reinterpret_cast<const float4*>(r0 + 3 * DD + lane * 4);
    const float4 c3 = *reinterpret_cast<const float4*>(r0 + 3 * DD + 128 + lane * 4);

    float d0 = a0.x * wa.x + a0.y * wa.y + a0.z * wa.z + a0.w * wa.w
             + c0.x * wb.x + c0.y * wb.y + c0.z * wb.z + c0.w * wb.w;
    float d1 = a1.x * wa.x + a1.y * wa.y + a1.z * wa.z + a1.w * wa.w
             + c1.x * wb.x + c1.y * wb.y + c1.z * wb.z + c1.w * wb.w;
    float d2 = a2.x * wa.x + a2.y * wa.y + a2.z * wa.z + a2.w * wa.w
             + c2.x * wb.x + c2.y * wb.y + c2.z * wb.z + c2.w * wb.w;
    float d3 = a3.x * wa.x + a3.y * wa.y + a3.z * wa.z + a3.w * wa.w
             + c3.x * wb.x + c3.y * wb.y + c3.z * wb.z + c3.w * wb.w;

    #pragma unroll
    for (int o = 16; o; o >>= 1) {
        d0 += __shfl_xor_sync(0xffffffffu, d0, o);
        d1 += __shfl_xor_sync(0xffffffffu, d1, o);
        d2 += __shfl_xor_sync(0xffffffffu, d2, o);
        d3 += __shfl_xor_sync(0xffffffffu, d3, o);
    }
    if (lane == 0) {
        g_score[row0]     = d0;
        g_score[row0 + 1] = d1;
        g_score[row0 + 2] = d2;
        g_score[row0 + 3] = d3;
    }
}

// ---------------- Kernel 2: radix top-K select (block per graph, 512 thr) ----------------
__global__ __launch_bounds__(512)
void rank_kernel(const float* __restrict__ w)
{
    __shared__ unsigned hist[256];
    __shared__ unsigned sscan[256];   // sscan[v] = # active nodes with byte >= v
    __shared__ unsigned s_t, s_gt, s_remk;
    __shared__ int s_wcnt[16];
    __shared__ float s_inv;

    const int tid  = threadIdx.x;
    const int lane = tid & 31;
    const int warp = tid >> 5;
    const int b    = blockIdx.x;

    if (warp == 0) {
        float ssq = 0.f;
        #pragma unroll
        for (int i = 0; i < 8; i++) { float v = w[lane + i * 32]; ssq += v * v; }
        #pragma unroll
        for (int o = 16; o; o >>= 1) ssq += __shfl_xor_sync(0xffffffffu, ssq, o);
        if (lane == 0) s_inv = rsqrtf(ssq);
    }
    if (tid == 0) s_remk = KK;

    const float s = g_score[b * NN + tid];
    const unsigned bits = __float_as_uint(s);
    const unsigned key  = (bits & 0x80000000u) ? ~bits : (bits | 0x80000000u);

    bool active = true, selected = false;

    #pragma unroll
    for (int pass = 0; pass < 4; ++pass) {
        if (tid < 256) hist[tid] = 0u;
        __syncthreads();
        const unsigned byt = (key >> (24 - 8 * pass)) & 0xFFu;
        if (active) atomicAdd(&hist[byt], 1u);
        __syncthreads();

        // suffix scan of hist by warp 0: lane l owns bins [8l, 8l+8)
        if (warp == 0) {
            unsigned tot = 0;
            #pragma unroll
            for (int j = 0; j < 8; j++) tot += hist[lane * 8 + j];
            unsigned suf = tot;
            #pragma unroll
            for (int o = 1; o < 32; o <<= 1) {
                unsigned t2 = __shfl_down_sync(0xffffffffu, suf, o);
                if (lane + o < 32) suf += t2;
            }
            unsigned run = suf - tot;
            #pragma unroll
            for (int j = 7; j >= 0; --j) {
                run += hist[lane * 8 + j];
                sscan[lane * 8 + j] = run;
            }
        }
        __syncthreads();

        const unsigned remk = s_remk;
        if (tid < 256) {
            const unsigned ge = sscan[tid];
            const unsigned gt = (tid == 255) ? 0u : sscan[tid + 1];
            if (ge >= remk && gt < remk) { s_t = (unsigned)tid; s_gt = gt; }
        }
        __syncthreads();

        const unsigned t = s_t;
        if (active) {
            if (byt > t)      { selected = true; active = false; }
            else if (byt < t) { active = false; }
        }
        if (tid == 0) s_remk = remk - s_gt;
        __syncthreads();
    }

    // ties at the K-th value: lowest indices win (jax.lax.top_k tie-break)
    {
        const unsigned m_act = __ballot_sync(0xffffffffu, active);
        if (lane == 0) s_wcnt[warp] = __popc(m_act);
        __syncthreads();
        if (tid == 0) {
            int run = 0;
            #pragma unroll
            for (int i = 0; i < 16; i++) { int c = s_wcnt[i]; s_wcnt[i] = run; run += c; }
        }
        __syncthreads();
        if (active) {
            const int irank = s_wcnt[warp] + __popc(m_act & ((1u << lane) - 1u));
            if ((unsigned)irank < s_remk) selected = true;
        }
        __syncthreads();
    }

    // deterministic compaction
    const unsigned m_sel = __ballot_sync(0xffffffffu, selected);
    if (lane == 0) s_wcnt[warp] = __popc(m_sel);
    __syncthreads();
    if (tid == 0) {
        int run = 0;
        #pragma unroll
        for (int i = 0; i < 16; i++) { int c = s_wcnt[i]; s_wcnt[i] = run; run += c; }
    }
    __syncthreads();
    if (selected) {
        const int slot = s_wcnt[warp] + __popc(m_sel & ((1u << lane) - 1u));
        g_sel[b * KK + slot] = make_int2(tid, __float_as_int(tanhf(s * s_inv)));
    }
}

// ---------------- Kernel 3: gather + direct output ----------------
// block = (graph, col-half). 256 threads: tid&127 -> column within half,
// tid>>7 -> row chunk (128 rows). Intra-block smem reduce, write out directly.
__global__ __launch_bounds__(256)
void gather_out_kernel(const float* __restrict__ x, float* __restrict__ out)
{
    __shared__ int2  s_sel[KK];
    __shared__ float s_part[256];

    const int tid = threadIdx.x;
    const int b   = blockIdx.x >> 1;
    const int h   = blockIdx.x & 1;

    s_sel[tid] = g_sel[b * KK + tid];
    __syncthreads();

    const int col = (tid & 127) + h * 128;
    const int rh  = tid >> 7;            // 0 or 1: rows [rh*128, rh*128+128)
    const float* xb = x + (size_t)b * NN * DD + col;

    float a0 = 0.f, a1 = 0.f, a2 = 0.f, a3 = 0.f;
    const int k0 = rh * 128;
    #pragma unroll 8
    for (int k = k0; k < k0 + 128; k += 4) {
        const int2 p0 = s_sel[k];
        const int2 p1 = s_sel[k + 1];
        const int2 p2 = s_sel[k + 2];
        const int2 p3 = s_sel[k + 3];
        a0 += xb[(size_t)p0.x * DD] * __int_as_float(p0.y);
        a1 += xb[(size_t)p1.x * DD] * __int_as_float(p1.y);
        a2 += xb[(size_t)p2.x * DD] * __int_as_float(p2.y);
        a3 += xb[(size_t)p3.x * DD] * __int_as_float(p3.y);
    }
    s_part[tid] = (a0 + a1) + (a2 + a3);
    __syncthreads();

    if (tid < 128) {
        out[b * DD + h * 128 + tid] =
            (s_part[tid] + s_part[tid + 128]) * (1.0f / (float)KK);
    }
}

extern "C" void kernel_launch(void* const* d_in, const int* in_sizes, int n_in,
                              void* d_out, int out_size)
{
    (void)in_sizes; (void)n_in; (void)out_size;
    const float* x = (const float*)d_in[0];
    const float* w = (const float*)d_in[1];
    float* out = (float*)d_out;

    score_kernel<<<(BB * NN) / 32, 256>>>(x, w);
    rank_kernel<<<BB, 512>>>(w);
    gather_out_kernel<<<BB * 2, 256>>>(x, out);
}

// round 11
// speedup vs baseline: 1.1732x; 1.1732x over previous
#include <cuda_runtime.h>
#include <cuda_bf16.h>

// TopKPool_16372415332892
// out[b] = (1/K) * sum_{topK rows} x[row] * tanh((x[row].w)/||w||)
// B=256, N=512, D=256, K=256. edge_index/batch dead inputs.

#define BB 256
#define NN 512
#define DD 256
#define KK 256

__device__ float g_score[BB * NN];     // raw dot products (selection monotone in this)
__device__ int2  g_sel[BB * KK];       // {node idx, gate bits}, compacted by rank
__device__ float g_part[BB * 4 * DD];  // gather partials (4 chunks/graph)
__device__ int   g_cnt[BB];            // arrival counters for last-block reduce

// ---------------- Kernel 1: scores (2 rows/warp, wide grid) ----------------
// grid = B*N/16 = 8192 blocks, 256 threads. Block 0 also zeroes g_cnt.
__global__ __launch_bounds__(256)
void score_kernel(const float* __restrict__ x, const float* __restrict__ w)
{
    if (blockIdx.x == 0 && threadIdx.x < BB) g_cnt[threadIdx.x] = 0;

    const int lane = threadIdx.x & 31;
    const int warp = threadIdx.x >> 5;
    const int row0 = blockIdx.x * 16 + warp * 2;

    const float4 wa = *reinterpret_cast<const float4*>(w + lane * 4);
    const float4 wb = *reinterpret_cast<const float4*>(w + 128 + lane * 4);

    const float* r0 = x + (size_t)row0 * DD;
    const float* r1 = r0 + DD;
    const float4 a0 = *reinterpret_cast<const float4*>(r0 + lane * 4);
    const float4 c0 = *reinterpret_cast<const float4*>(r0 + 128 + lane * 4);
    const float4 a1 = *reinterpret_cast<const float4*>(r1 + lane * 4);
    const float4 c1 = *reinterpret_cast<const float4*>(r1 + 128 + lane * 4);

    float d0 = a0.x * wa.x + a0.y * wa.y + a0.z * wa.z + a0.w * wa.w
             + c0.x * wb.x + c0.y * wb.y + c0.z * wb.z + c0.w * wb.w;
    float d1 = a1.x * wa.x + a1.y * wa.y + a1.z * wa.z + a1.w * wa.w
             + c1.x * wb.x + c1.y * wb.y + c1.z * wb.z + c1.w * wb.w;
    #pragma unroll
    for (int o = 16; o; o >>= 1) {
        d0 += __shfl_xor_sync(0xffffffffu, d0, o);
        d1 += __shfl_xor_sync(0xffffffffu, d1, o);
    }
    if (lane == 0) {
        g_score[row0]     = d0;
        g_score[row0 + 1] = d1;
    }
}

// ---------------- Kernel 2: radix top-K select (block per graph, 512 thr) ----------------
__global__ __launch_bounds__(512)
void rank_kernel(const float* __restrict__ w)
{
    __shared__ unsigned hist[256];
    __shared__ unsigned sscan[256];   // sscan[v] = # active nodes with byte >= v
    __shared__ unsigned s_t, s_gt, s_remk;
    __shared__ int s_wcnt[16];
    __shared__ float s_inv;

    const int tid  = threadIdx.x;
    const int lane = tid & 31;
    const int warp = tid >> 5;
    const int b    = blockIdx.x;

    if (warp == 0) {
        float ssq = 0.f;
        #pragma unroll
        for (int i = 0; i < 8; i++) { float v = w[lane + i * 32]; ssq += v * v; }
        #pragma unroll
        for (int o = 16; o; o >>= 1) ssq += __shfl_xor_sync(0xffffffffu, ssq, o);
        if (lane == 0) s_inv = rsqrtf(ssq);
    }
    if (tid == 0) s_remk = KK;

    const float s = g_score[b * NN + tid];
    const unsigned bits = __float_as_uint(s);
    const unsigned key  = (bits & 0x80000000u) ? ~bits : (bits | 0x80000000u);

    bool active = true, selected = false;

    #pragma unroll
    for (int pass = 0; pass < 4; ++pass) {
        if (tid < 256) hist[tid] = 0u;
        __syncthreads();
        const unsigned byt = (key >> (24 - 8 * pass)) & 0xFFu;
        if (active) atomicAdd(&hist[byt], 1u);
        __syncthreads();

        // suffix scan of hist by warp 0: lane l owns bins [8l, 8l+8)
        if (warp == 0) {
            unsigned tot = 0;
            #pragma unroll
            for (int j = 0; j < 8; j++) tot += hist[lane * 8 + j];
            unsigned suf = tot;
            #pragma unroll
            for (int o = 1; o < 32; o <<= 1) {
                unsigned t2 = __shfl_down_sync(0xffffffffu, suf, o);
                if (lane + o < 32) suf += t2;
            }
            unsigned run = suf - tot;
            #pragma unroll
            for (int j = 7; j >= 0; --j) {
                run += hist[lane * 8 + j];
                sscan[lane * 8 + j] = run;
            }
        }
        __syncthreads();

        const unsigned remk = s_remk;
        if (tid < 256) {
            const unsigned ge = sscan[tid];
            const unsigned gt = (tid == 255) ? 0u : sscan[tid + 1];
            if (ge >= remk && gt < remk) { s_t = (unsigned)tid; s_gt = gt; }
        }
        __syncthreads();

        const unsigned t = s_t;
        if (active) {
            if (byt > t)      { selected = true; active = false; }
            else if (byt < t) { active = false; }
        }
        if (tid == 0) s_remk = remk - s_gt;
        __syncthreads();
    }

    // ties at the K-th value: lowest indices win (jax.lax.top_k tie-break)
    {
        const unsigned m_act = __ballot_sync(0xffffffffu, active);
        if (lane == 0) s_wcnt[warp] = __popc(m_act);
        __syncthreads();
        if (tid == 0) {
            int run = 0;
            #pragma unroll
            for (int i = 0; i < 16; i++) { int c = s_wcnt[i]; s_wcnt[i] = run; run += c; }
        }
        __syncthreads();
        if (active) {
            const int irank = s_wcnt[warp] + __popc(m_act & ((1u << lane) - 1u));
            if ((unsigned)irank < s_remk) selected = true;
        }
        __syncthreads();
    }

    // deterministic compaction
    const unsigned m_sel = __ballot_sync(0xffffffffu, selected);
    if (lane == 0) s_wcnt[warp] = __popc(m_sel);
    __syncthreads();
    if (tid == 0) {
        int run = 0;
        #pragma unroll
        for (int i = 0; i < 16; i++) { int c = s_wcnt[i]; s_wcnt[i] = run; run += c; }
    }
    __syncthreads();
    if (selected) {
        const int slot = s_wcnt[warp] + __popc(m_sel & ((1u << lane) - 1u));
        g_sel[b * KK + slot] = make_int2(tid, __float_as_int(tanhf(s * s_inv)));
    }
}

// ---------------- Kernel 3: gather (4 blocks/graph) + last-block reduce ----------------
// grid = B*4 blocks, 256 threads. Chunk c of graph b accumulates rows [c*64, c*64+64)
// into g_part; the 4th arriving block for graph b sums the 4 partials (fixed order,
// fixed slots -> deterministic values) and writes out directly.
__global__ __launch_bounds__(256)
void gather_kernel(const float* __restrict__ x, float* __restrict__ out)
{
    __shared__ int2 s_sel[64];
    __shared__ int  s_last;

    const int tid = threadIdx.x;
    const int b   = blockIdx.x >> 2;
    const int c   = blockIdx.x & 3;

    if (tid < 64) s_sel[tid] = g_sel[b * KK + c * 64 + tid];
    __syncthreads();

    const float* xb = x + (size_t)b * NN * DD + tid;
    float a0 = 0.f, a1 = 0.f, a2 = 0.f, a3 = 0.f;
    #pragma unroll 16
    for (int k = 0; k < 64; k += 4) {
        const int2 p0 = s_sel[k];
        const int2 p1 = s_sel[k + 1];
        const int2 p2 = s_sel[k + 2];
        const int2 p3 = s_sel[k + 3];
        a0 += xb[(size_t)p0.x * DD] * __int_as_float(p0.y);
        a1 += xb[(size_t)p1.x * DD] * __int_as_float(p1.y);
        a2 += xb[(size_t)p2.x * DD] * __int_as_float(p2.y);
        a3 += xb[(size_t)p3.x * DD] * __int_as_float(p3.y);
    }
    g_part[blockIdx.x * DD + tid] = (a0 + a1) + (a2 + a3);

    // last block of this graph folds the partials
    __threadfence();
    __syncthreads();
    if (tid == 0) s_last = (atomicAdd(&g_cnt[b], 1) == 3);
    __syncthreads();
    if (s_last) {
        const float* p = g_part + b * 4 * DD;
        const float v = (p[tid] + p[DD + tid]) + (p[2 * DD + tid] + p[3 * DD + tid]);
        out[b * DD + tid] = v * (1.0f / (float)KK);
    }
}

extern "C" void kernel_launch(void* const* d_in, const int* in_sizes, int n_in,
                              void* d_out, int out_size)
{
    (void)in_sizes; (void)n_in; (void)out_size;
    const float* x = (const float*)d_in[0];
    const float* w = (const float*)d_in[1];
    float* out = (float*)d_out;

    score_kernel<<<(BB * NN) / 16, 256>>>(x, w);
    rank_kernel<<<BB, 512>>>(w);
    gather_kernel<<<BB * 4, 256>>>(x, out);
}